// round 14
// baseline (speedup 1.0000x reference)
#include <cuda_runtime.h>
#include <cuda_bf16.h>
#include <math.h>
#include <stdint.h>

#define NN 50000
#define EE 800000
#define FIN 256
#define HID 96
#define NCLS 32
#define NEG 0.2f
#define MAXDEG 64
#define NB_ROWS 6250          // NN/8, warp per row
#define NB_SCAT 3125          // EE/256
#define GEMM_BLKS 391         // ceil(NN/128)
#define AUX_BLKS 49           // zero g_cursor (49*256*4 >= NN)

// ---------------- scratch ----------------------------------------------------
__device__ __align__(16) float g_h1[NN * HID];
__device__ __align__(16) float g_h2[NN * NCLS];
__device__ float g_as1[NN], g_ad1[NN];
__device__ float g_as2[NN], g_ad2[NN];
__device__ __align__(16) int g_cursor[NN];
__device__ int   g_csrc[NN * MAXDEG];   // padded adjacency, stride 64 per dst

__device__ __forceinline__ float leaky(float e) { return e > 0.f ? e : NEG * e; }

// per-warp edge-index dtype detection (int64 vs int32)
__device__ __forceinline__ int detect64(const void* ei) {
    const long long* p = (const long long*)ei;
    int lane = threadIdx.x & 31;
    long long v0 = p[lane], v1 = p[lane + 32];
    bool ok = (v0 >= 0) && (v0 < NN) && (v1 >= 0) && (v1 < NN);
    return __all_sync(~0u, ok);
}
__device__ __forceinline__ int load_idx(const void* ei, int is64, int half, int e) {
    if (is64) return (int)((const long long*)ei)[(size_t)half * EE + e];
    return ((const int*)ei)[(size_t)half * EE + e];
}

__device__ __forceinline__ uint32_t packbf(float lo, float hi) {
    uint32_t d;
    asm("cvt.rn.bf16x2.f32 %0, %1, %2;" : "=r"(d) : "f"(hi), "f"(lo));
    return d;
}

#define MMA_BF16(c, a, b)                                                       \
    asm volatile("mma.sync.aligned.m16n8k16.row.col.f32.bf16.bf16.f32 "        \
                 "{%0,%1,%2,%3}, {%4,%5,%6,%7}, {%8,%9}, {%0,%1,%2,%3};"       \
                 : "+f"((c)[0]), "+f"((c)[1]), "+f"((c)[2]), "+f"((c)[3])      \
                 : "r"((a)[0]), "r"((a)[1]), "r"((a)[2]), "r"((a)[3]),         \
                   "r"((b)[0]), "r"((b)[1]))

// 1: GEMM1 h1 = x @ W1, bf16 mma.sync 3-term split + aux zero blocks ---------
#define ASTR 20
#define BSTR 20
__global__ void __launch_bounds__(256) k_gemm1(const float* __restrict__ x,
                                               const float* __restrict__ W) {
    int tid = threadIdx.x;
    if (blockIdx.x >= GEMM_BLKS) {
        int a = (blockIdx.x - GEMM_BLKS) * 256 + tid;
        if (a < NN / 4 + 1) {
            int4 z = make_int4(0, 0, 0, 0);
            if (a * 4 + 3 < NN) ((int4*)g_cursor)[a] = z;
            else for (int q = a * 4; q < NN; q++) g_cursor[q] = 0;
        }
        return;
    }
    __shared__ uint32_t Ah[128 * ASTR], Al[128 * ASTR];
    __shared__ uint32_t Bh[HID * BSTR], Bl[HID * BSTR];
    int wid = tid >> 5, lane = tid & 31;
    int g = lane >> 2, t = lane & 3;
    int wm = wid >> 1, wn = wid & 1;
    int row0 = blockIdx.x * 128;

    float c[2][6][4];
#pragma unroll
    for (int mt = 0; mt < 2; mt++)
#pragma unroll
        for (int nt = 0; nt < 6; nt++)
#pragma unroll
            for (int q = 0; q < 4; q++) c[mt][nt][q] = 0.f;

    for (int kc = 0; kc < 8; kc++) {
        int k0 = kc * 32;
        __syncthreads();
#pragma unroll
        for (int it = 0; it < 4; it++) {
            int idx = tid + 256 * it;
            int m = idx >> 3, k4 = idx & 7;
            int gr = row0 + m; if (gr >= NN) gr = NN - 1;
            float4 v = *(const float4*)(x + (size_t)gr * FIN + k0 + k4 * 4);
            uint32_t h0 = packbf(v.x, v.y);
            uint32_t h1 = packbf(v.z, v.w);
            float hx = __uint_as_float(h0 << 16), hy = __uint_as_float(h0 & 0xffff0000u);
            float hz = __uint_as_float(h1 << 16), hw = __uint_as_float(h1 & 0xffff0000u);
            uint32_t l0 = packbf(v.x - hx, v.y - hy);
            uint32_t l1 = packbf(v.z - hz, v.w - hw);
            Ah[m * ASTR + k4 * 2]     = h0;
            Ah[m * ASTR + k4 * 2 + 1] = h1;
            Al[m * ASTR + k4 * 2]     = l0;
            Al[m * ASTR + k4 * 2 + 1] = l1;
        }
#pragma unroll
        for (int it = 0; it < 2; it++) {
            int task = tid + 256 * it;
            if (task < 384) {
                int kp = task / 24, n4 = (task % 24) * 4;
                float4 r0 = *(const float4*)(W + (size_t)(k0 + 2 * kp) * HID + n4);
                float4 r1 = *(const float4*)(W + (size_t)(k0 + 2 * kp + 1) * HID + n4);
                float a0[4] = {r0.x, r0.y, r0.z, r0.w};
                float a1[4] = {r1.x, r1.y, r1.z, r1.w};
#pragma unroll
                for (int u = 0; u < 4; u++) {
                    uint32_t h = packbf(a0[u], a1[u]);
                    float hx = __uint_as_float(h << 16), hy = __uint_as_float(h & 0xffff0000u);
                    uint32_t l = packbf(a0[u] - hx, a1[u] - hy);
                    Bh[(n4 + u) * BSTR + kp] = h;
                    Bl[(n4 + u) * BSTR + kp] = l;
                }
            }
        }
        __syncthreads();
#pragma unroll
        for (int ks = 0; ks < 2; ks++) {
            int kp0 = ks * 8 + t;
            uint32_t ah[2][4], al[2][4], bh[6][2], bl[6][2];
#pragma unroll
            for (int mt = 0; mt < 2; mt++) {
                int rA = (wm * 32 + mt * 16 + g) * ASTR;
                ah[mt][0] = Ah[rA + kp0];
                ah[mt][1] = Ah[rA + 8 * ASTR + kp0];
                ah[mt][2] = Ah[rA + kp0 + 4];
                ah[mt][3] = Ah[rA + 8 * ASTR + kp0 + 4];
                al[mt][0] = Al[rA + kp0];
                al[mt][1] = Al[rA + 8 * ASTR + kp0];
                al[mt][2] = Al[rA + kp0 + 4];
                al[mt][3] = Al[rA + 8 * ASTR + kp0 + 4];
            }
#pragma unroll
            for (int nt = 0; nt < 6; nt++) {
                int cB = (wn * 48 + nt * 8 + g) * BSTR;
                bh[nt][0] = Bh[cB + kp0];
                bh[nt][1] = Bh[cB + kp0 + 4];
                bl[nt][0] = Bl[cB + kp0];
                bl[nt][1] = Bl[cB + kp0 + 4];
            }
#pragma unroll
            for (int mt = 0; mt < 2; mt++)
#pragma unroll
                for (int nt = 0; nt < 6; nt++) {
                    MMA_BF16(c[mt][nt], ah[mt], bh[nt]);
                    MMA_BF16(c[mt][nt], ah[mt], bl[nt]);
                    MMA_BF16(c[mt][nt], al[mt], bh[nt]);
                }
        }
    }
#pragma unroll
    for (int mt = 0; mt < 2; mt++) {
        int r0 = row0 + wm * 32 + mt * 16 + g;
        int r1 = r0 + 8;
#pragma unroll
        for (int nt = 0; nt < 6; nt++) {
            int col = wn * 48 + nt * 8 + 2 * t;
            if (r0 < NN) *(float2*)(g_h1 + (size_t)r0 * HID + col) = make_float2(c[mt][nt][0], c[mt][nt][1]);
            if (r1 < NN) *(float2*)(g_h1 + (size_t)r1 * HID + col) = make_float2(c[mt][nt][2], c[mt][nt][3]);
        }
    }
}

// 2: fused padded scatter (blocks >= NB_ROWS) + alpha1 dots (blocks < NB_ROWS)
__global__ void __launch_bounds__(256) k_scatter_alpha(const void* ei,
                                                       const float* __restrict__ a1s,
                                                       const float* __restrict__ a1d) {
    int tid = threadIdx.x;
    if (blockIdx.x < NB_ROWS) {
        int warp = tid >> 5, lane = tid & 31;
        int r = blockIdx.x * 8 + warp;
        if (r >= NN) return;
        float s1 = 0.f, s2 = 0.f;
#pragma unroll
        for (int v = 0; v < 3; v++) {
            float hv = g_h1[r * HID + lane + 32 * v];
            s1 += hv * a1s[lane + 32 * v];
            s2 += hv * a1d[lane + 32 * v];
        }
#pragma unroll
        for (int o = 16; o; o >>= 1) {
            s1 += __shfl_xor_sync(~0u, s1, o);
            s2 += __shfl_xor_sync(~0u, s2, o);
        }
        if (lane == 0) { g_as1[r] = s1; g_ad1[r] = s2; }
    } else {
        int is64 = detect64(ei);
        int e = (blockIdx.x - NB_ROWS) * 256 + tid;
        if (e >= EE) return;
        int s = load_idx(ei, is64, 0, e);
        int d = load_idx(ei, is64, 1, e);
        int pos = atomicAdd(&g_cursor[d], 1);
        if (pos < MAXDEG) g_csrc[d * MAXDEG + pos] = s;
    }
}

// 3: layer-1 agg (4 edges in flight, float4 gathers) + ELU + GEMM2 + alpha2
__global__ void __launch_bounds__(256) k_agg1(const float* __restrict__ b1,
                                              const float* __restrict__ W2,
                                              const float* __restrict__ a2s,
                                              const float* __restrict__ a2d) {
    __shared__ float ws[HID * NCLS];
    __shared__ float sb1[HID];
    __shared__ float sa2[NCLS], sd2[NCLS];
    __shared__ float sh1e[8][HID];
    int tid = threadIdx.x;
    for (int l = tid; l < HID * NCLS; l += 256) ws[l] = W2[l];
    if (tid < HID) sb1[tid] = b1[tid];
    if (tid < NCLS) { sa2[tid] = a2s[tid]; sd2[tid] = a2d[tid]; }
    __syncthreads();
    int warp = tid >> 5, lane = tid & 31;
    int grp = lane >> 3, sub = lane & 7;
    int i = blockIdx.x * 8 + warp;
    if (i >= NN) return;

    const float4* hbase = (const float4*)g_h1;
    int deg = g_cursor[i]; if (deg > MAXDEG) deg = MAXDEG;
    int base = i * MAXDEG;
    float adi = g_ad1[i];
    float w_self = __expf(leaky(g_as1[i] + adi));
    float acc[12];
    if (grp == 0) {
        const float4* hp = hbase + i * 24 + sub * 3;
#pragma unroll
        for (int k = 0; k < 3; k++) {
            float4 v = hp[k];
            acc[4 * k] = w_self * v.x; acc[4 * k + 1] = w_self * v.y;
            acc[4 * k + 2] = w_self * v.z; acc[4 * k + 3] = w_self * v.w;
        }
    } else {
#pragma unroll
        for (int q = 0; q < 12; q++) acc[q] = 0.f;
    }
    float dsum = (lane == 0) ? w_self : 0.f;

    for (int j0 = 0; j0 < deg; j0 += 32) {
        int jj = j0 + lane;
        int cnt = deg - j0; if (cnt > 32) cnt = 32;
        int s = (jj < deg) ? g_csrc[base + jj] : 0;
        float w = (jj < deg) ? __expf(leaky(g_as1[s] + adi)) : 0.f;
        dsum += w;
        int nst = (cnt + 3) >> 2;
        for (int t = 0; t < nst; t++) {
            int e = t * 4 + grp;
            int ss = __shfl_sync(~0u, s, e);
            float ww = __shfl_sync(~0u, w, e);
            const float4* hp = hbase + ss * 24 + sub * 3;
#pragma unroll
            for (int k = 0; k < 3; k++) {
                float4 v = hp[k];
                acc[4 * k] += ww * v.x; acc[4 * k + 1] += ww * v.y;
                acc[4 * k + 2] += ww * v.z; acc[4 * k + 3] += ww * v.w;
            }
        }
    }
#pragma unroll
    for (int o = 16; o; o >>= 1) dsum += __shfl_xor_sync(~0u, dsum, o);
#pragma unroll
    for (int q = 0; q < 12; q++) {
        acc[q] += __shfl_xor_sync(~0u, acc[q], 8);
        acc[q] += __shfl_xor_sync(~0u, acc[q], 16);
    }
    float inv = 1.f / dsum;
    float o[12];
#pragma unroll
    for (int q = 0; q < 12; q++) {
        float v = acc[q] * inv + sb1[sub * 12 + q];
        o[q] = v > 0.f ? v : (__expf(v) - 1.f);
    }
    if (lane < 8) {
#pragma unroll
        for (int q = 0; q < 12; q++) sh1e[warp][lane * 12 + q] = o[q];
    }
    __syncwarp();
    float a2 = 0.f;
#pragma unroll 16
    for (int k = 0; k < HID; k++) a2 += sh1e[warp][k] * ws[k * NCLS + lane];
    g_h2[i * NCLS + lane] = a2;
    float s1 = a2 * sa2[lane], s2 = a2 * sd2[lane];
#pragma unroll
    for (int off = 16; off; off >>= 1) {
        s1 += __shfl_xor_sync(~0u, s1, off);
        s2 += __shfl_xor_sync(~0u, s2, off);
    }
    if (lane == 0) { g_as2[i] = s1; g_ad2[i] = s2; }
}

// 4: layer-2 agg + bias + log_softmax -> out
__global__ void __launch_bounds__(256) k_agg2(const float* __restrict__ b2,
                                              float* __restrict__ outp) {
    int tid = threadIdx.x;
    int warp = tid >> 5, lane = tid & 31;
    int grp = lane >> 3, sub = lane & 7;
    int i = blockIdx.x * 8 + warp;
    if (i >= NN) return;
    const float4* hbase = (const float4*)g_h2;
    int deg = g_cursor[i]; if (deg > MAXDEG) deg = MAXDEG;
    int base = i * MAXDEG;
    float adi = g_ad2[i];
    float w_self = __expf(leaky(g_as2[i] + adi));
    float acc[4];
    if (grp == 0) {
        float4 v = hbase[i * 8 + sub];
        acc[0] = w_self * v.x; acc[1] = w_self * v.y;
        acc[2] = w_self * v.z; acc[3] = w_self * v.w;
    } else {
        acc[0] = acc[1] = acc[2] = acc[3] = 0.f;
    }
    float dsum = (lane == 0) ? w_self : 0.f;
    for (int j0 = 0; j0 < deg; j0 += 32) {
        int jj = j0 + lane;
        int cnt = deg - j0; if (cnt > 32) cnt = 32;
        int s = (jj < deg) ? g_csrc[base + jj] : 0;
        float w = (jj < deg) ? __expf(leaky(g_as2[s] + adi)) : 0.f;
        dsum += w;
        int nst = (cnt + 3) >> 2;
        for (int t = 0; t < nst; t++) {
            int e = t * 4 + grp;
            int ss = __shfl_sync(~0u, s, e);
            float ww = __shfl_sync(~0u, w, e);
            float4 v = hbase[ss * 8 + sub];
            acc[0] += ww * v.x; acc[1] += ww * v.y;
            acc[2] += ww * v.z; acc[3] += ww * v.w;
        }
    }
#pragma unroll
    for (int o = 16; o; o >>= 1) dsum += __shfl_xor_sync(~0u, dsum, o);
#pragma unroll
    for (int q = 0; q < 4; q++) {
        acc[q] += __shfl_xor_sync(~0u, acc[q], 8);
        acc[q] += __shfl_xor_sync(~0u, acc[q], 16);
    }
    float inv = 1.f / dsum;
    float o[4];
    float mx = -1e30f;
#pragma unroll
    for (int q = 0; q < 4; q++) {
        o[q] = acc[q] * inv + b2[sub * 4 + q];
        mx = fmaxf(mx, o[q]);
    }
#pragma unroll
    for (int off = 1; off < 8; off <<= 1) mx = fmaxf(mx, __shfl_xor_sync(~0u, mx, off));
    float se = 0.f;
#pragma unroll
    for (int q = 0; q < 4; q++) se += __expf(o[q] - mx);
#pragma unroll
    for (int off = 1; off < 8; off <<= 1) se += __shfl_xor_sync(~0u, se, off);
    float lse = mx + __logf(se);
    if (lane < 8) {
        float4 r = make_float4(o[0] - lse, o[1] - lse, o[2] - lse, o[3] - lse);
        *((float4*)(outp + i * NCLS) + sub) = r;
    }
}

// ---------------- launch -----------------------------------------------------
extern "C" void kernel_launch(void* const* d_in, const int* in_sizes, int n_in,
                              void* d_out, int out_size) {
    const float* x   = (const float*)d_in[0];
    const void*  ei  = d_in[1];
    const float* W1  = (const float*)d_in[2];
    const float* a1s = (const float*)d_in[3];
    const float* a1d = (const float*)d_in[4];
    const float* b1  = (const float*)d_in[5];
    const float* W2  = (const float*)d_in[6];
    const float* a2s = (const float*)d_in[7];
    const float* a2d = (const float*)d_in[8];
    const float* b2  = (const float*)d_in[9];
    float* out = (float*)d_out;

    k_gemm1<<<GEMM_BLKS + AUX_BLKS, 256>>>(x, W1);             // 0 (gemm + zero cursor)
    k_scatter_alpha<<<NB_ROWS + NB_SCAT, 256>>>(ei, a1s, a1d); // 1
    k_agg1<<<NB_ROWS, 256>>>(b1, W2, a2s, a2d);                // 2
    k_agg2<<<NB_ROWS, 256>>>(b2, out);                         // 3
}

// round 15
// speedup vs baseline: 1.0527x; 1.0527x over previous
#include <cuda_runtime.h>
#include <cuda_bf16.h>
#include <math.h>
#include <stdint.h>

#define NN 50000
#define EE 800000
#define FIN 256
#define HID 96
#define NCLS 32
#define NEG 0.2f
#define MAXDEG 64
#define NB_ROWS 6250          // NN/8, warp per row
#define NB_SCAT4 782          // ceil(EE / (256*4)) edge blocks, 4 edges/thread
#define GEMM_BLKS 391         // ceil(NN/128)
#define AUX_BLKS 49           // zero g_cursor

// ---------------- scratch ----------------------------------------------------
__device__ __align__(16) float g_h1[NN * HID];
__device__ __align__(16) float g_h2[NN * NCLS];
__device__ float g_as1[NN], g_ad1[NN];
__device__ float g_as2[NN], g_ad2[NN];
__device__ __align__(16) int g_cursor[NN];
__device__ int   g_csrc[NN * MAXDEG];   // padded adjacency, stride 64 per dst

__device__ __forceinline__ float leaky(float e) { return e > 0.f ? e : NEG * e; }

// per-warp edge-index dtype detection (int64 vs int32)
__device__ __forceinline__ int detect64(const void* ei) {
    const long long* p = (const long long*)ei;
    int lane = threadIdx.x & 31;
    long long v0 = p[lane], v1 = p[lane + 32];
    bool ok = (v0 >= 0) && (v0 < NN) && (v1 >= 0) && (v1 < NN);
    return __all_sync(~0u, ok);
}
__device__ __forceinline__ int load_idx(const void* ei, int is64, int half, int e) {
    if (is64) return (int)((const long long*)ei)[(size_t)half * EE + e];
    return ((const int*)ei)[(size_t)half * EE + e];
}

__device__ __forceinline__ uint32_t packbf(float lo, float hi) {
    uint32_t d;
    asm("cvt.rn.bf16x2.f32 %0, %1, %2;" : "=r"(d) : "f"(hi), "f"(lo));
    return d;
}

#define MMA_BF16(c, a, b)                                                       \
    asm volatile("mma.sync.aligned.m16n8k16.row.col.f32.bf16.bf16.f32 "        \
                 "{%0,%1,%2,%3}, {%4,%5,%6,%7}, {%8,%9}, {%0,%1,%2,%3};"       \
                 : "+f"((c)[0]), "+f"((c)[1]), "+f"((c)[2]), "+f"((c)[3])      \
                 : "r"((a)[0]), "r"((a)[1]), "r"((a)[2]), "r"((a)[3]),         \
                   "r"((b)[0]), "r"((b)[1]))

// 1: GEMM1 h1 = x @ W1, bf16 mma.sync 3-term split + aux zero blocks ---------
#define ASTR 20
#define BSTR 20
__global__ void __launch_bounds__(256) k_gemm1(const float* __restrict__ x,
                                               const float* __restrict__ W) {
    int tid = threadIdx.x;
    if (blockIdx.x >= GEMM_BLKS) {
        int a = (blockIdx.x - GEMM_BLKS) * 256 + tid;
        if (a < NN / 4 + 1) {
            int4 z = make_int4(0, 0, 0, 0);
            if (a * 4 + 3 < NN) ((int4*)g_cursor)[a] = z;
            else for (int q = a * 4; q < NN; q++) g_cursor[q] = 0;
        }
        return;
    }
    __shared__ uint32_t Ah[128 * ASTR], Al[128 * ASTR];
    __shared__ uint32_t Bh[HID * BSTR], Bl[HID * BSTR];
    int wid = tid >> 5, lane = tid & 31;
    int g = lane >> 2, t = lane & 3;
    int wm = wid >> 1, wn = wid & 1;
    int row0 = blockIdx.x * 128;

    float c[2][6][4];
#pragma unroll
    for (int mt = 0; mt < 2; mt++)
#pragma unroll
        for (int nt = 0; nt < 6; nt++)
#pragma unroll
            for (int q = 0; q < 4; q++) c[mt][nt][q] = 0.f;

    for (int kc = 0; kc < 8; kc++) {
        int k0 = kc * 32;
        __syncthreads();
#pragma unroll
        for (int it = 0; it < 4; it++) {
            int idx = tid + 256 * it;
            int m = idx >> 3, k4 = idx & 7;
            int gr = row0 + m; if (gr >= NN) gr = NN - 1;
            float4 v = *(const float4*)(x + (size_t)gr * FIN + k0 + k4 * 4);
            uint32_t h0 = packbf(v.x, v.y);
            uint32_t h1 = packbf(v.z, v.w);
            float hx = __uint_as_float(h0 << 16), hy = __uint_as_float(h0 & 0xffff0000u);
            float hz = __uint_as_float(h1 << 16), hw = __uint_as_float(h1 & 0xffff0000u);
            uint32_t l0 = packbf(v.x - hx, v.y - hy);
            uint32_t l1 = packbf(v.z - hz, v.w - hw);
            Ah[m * ASTR + k4 * 2]     = h0;
            Ah[m * ASTR + k4 * 2 + 1] = h1;
            Al[m * ASTR + k4 * 2]     = l0;
            Al[m * ASTR + k4 * 2 + 1] = l1;
        }
#pragma unroll
        for (int it = 0; it < 2; it++) {
            int task = tid + 256 * it;
            if (task < 384) {
                int kp = task / 24, n4 = (task % 24) * 4;
                float4 r0 = *(const float4*)(W + (size_t)(k0 + 2 * kp) * HID + n4);
                float4 r1 = *(const float4*)(W + (size_t)(k0 + 2 * kp + 1) * HID + n4);
                float a0[4] = {r0.x, r0.y, r0.z, r0.w};
                float a1[4] = {r1.x, r1.y, r1.z, r1.w};
#pragma unroll
                for (int u = 0; u < 4; u++) {
                    uint32_t h = packbf(a0[u], a1[u]);
                    float hx = __uint_as_float(h << 16), hy = __uint_as_float(h & 0xffff0000u);
                    uint32_t l = packbf(a0[u] - hx, a1[u] - hy);
                    Bh[(n4 + u) * BSTR + kp] = h;
                    Bl[(n4 + u) * BSTR + kp] = l;
                }
            }
        }
        __syncthreads();
#pragma unroll
        for (int ks = 0; ks < 2; ks++) {
            int kp0 = ks * 8 + t;
            uint32_t ah[2][4], al[2][4], bh[6][2], bl[6][2];
#pragma unroll
            for (int mt = 0; mt < 2; mt++) {
                int rA = (wm * 32 + mt * 16 + g) * ASTR;
                ah[mt][0] = Ah[rA + kp0];
                ah[mt][1] = Ah[rA + 8 * ASTR + kp0];
                ah[mt][2] = Ah[rA + kp0 + 4];
                ah[mt][3] = Ah[rA + 8 * ASTR + kp0 + 4];
                al[mt][0] = Al[rA + kp0];
                al[mt][1] = Al[rA + 8 * ASTR + kp0];
                al[mt][2] = Al[rA + kp0 + 4];
                al[mt][3] = Al[rA + 8 * ASTR + kp0 + 4];
            }
#pragma unroll
            for (int nt = 0; nt < 6; nt++) {
                int cB = (wn * 48 + nt * 8 + g) * BSTR;
                bh[nt][0] = Bh[cB + kp0];
                bh[nt][1] = Bh[cB + kp0 + 4];
                bl[nt][0] = Bl[cB + kp0];
                bl[nt][1] = Bl[cB + kp0 + 4];
            }
#pragma unroll
            for (int mt = 0; mt < 2; mt++)
#pragma unroll
                for (int nt = 0; nt < 6; nt++) {
                    MMA_BF16(c[mt][nt], ah[mt], bh[nt]);
                    MMA_BF16(c[mt][nt], ah[mt], bl[nt]);
                    MMA_BF16(c[mt][nt], al[mt], bh[nt]);
                }
        }
    }
#pragma unroll
    for (int mt = 0; mt < 2; mt++) {
        int r0 = row0 + wm * 32 + mt * 16 + g;
        int r1 = r0 + 8;
#pragma unroll
        for (int nt = 0; nt < 6; nt++) {
            int col = wn * 48 + nt * 8 + 2 * t;
            if (r0 < NN) *(float2*)(g_h1 + (size_t)r0 * HID + col) = make_float2(c[mt][nt][0], c[mt][nt][1]);
            if (r1 < NN) *(float2*)(g_h1 + (size_t)r1 * HID + col) = make_float2(c[mt][nt][2], c[mt][nt][3]);
        }
    }
}

// 2: fused padded scatter (4 edges/thread, MLP=4) + alpha1 dots ---------------
__global__ void __launch_bounds__(256) k_scatter_alpha(const void* ei,
                                                       const float* __restrict__ a1s,
                                                       const float* __restrict__ a1d) {
    int tid = threadIdx.x;
    if (blockIdx.x < NB_ROWS) {
        int warp = tid >> 5, lane = tid & 31;
        int r = blockIdx.x * 8 + warp;
        if (r >= NN) return;
        float s1 = 0.f, s2 = 0.f;
#pragma unroll
        for (int v = 0; v < 3; v++) {
            float hv = g_h1[r * HID + lane + 32 * v];
            s1 += hv * a1s[lane + 32 * v];
            s2 += hv * a1d[lane + 32 * v];
        }
#pragma unroll
        for (int o = 16; o; o >>= 1) {
            s1 += __shfl_xor_sync(~0u, s1, o);
            s2 += __shfl_xor_sync(~0u, s2, o);
        }
        if (lane == 0) { g_as1[r] = s1; g_ad1[r] = s2; }
    } else {
        int is64 = detect64(ei);
        int e0 = (blockIdx.x - NB_ROWS) * 1024 + tid;
        int s[4], d[4];
#pragma unroll
        for (int q = 0; q < 4; q++) {
            int e = e0 + q * 256;
            if (e < EE) {
                s[q] = load_idx(ei, is64, 0, e);
                d[q] = load_idx(ei, is64, 1, e);
            } else d[q] = -1;
        }
        int pos[4];
#pragma unroll
        for (int q = 0; q < 4; q++)
            if (d[q] >= 0) pos[q] = atomicAdd(&g_cursor[d[q]], 1);
#pragma unroll
        for (int q = 0; q < 4; q++)
            if (d[q] >= 0 && pos[q] < MAXDEG) g_csrc[d[q] * MAXDEG + pos[q]] = s[q];
    }
}

// 3: layer-1 agg (4 edges in flight, float4 gathers) + ELU + GEMM2 + alpha2
__global__ void __launch_bounds__(256) k_agg1(const float* __restrict__ b1,
                                              const float* __restrict__ W2,
                                              const float* __restrict__ a2s,
                                              const float* __restrict__ a2d) {
    __shared__ float ws[HID * NCLS];
    __shared__ float sb1[HID];
    __shared__ float sa2[NCLS], sd2[NCLS];
    __shared__ float sh1e[8][HID];
    int tid = threadIdx.x;
    for (int l = tid; l < HID * NCLS; l += 256) ws[l] = W2[l];
    if (tid < HID) sb1[tid] = b1[tid];
    if (tid < NCLS) { sa2[tid] = a2s[tid]; sd2[tid] = a2d[tid]; }
    __syncthreads();
    int warp = tid >> 5, lane = tid & 31;
    int grp = lane >> 3, sub = lane & 7;
    int i = blockIdx.x * 8 + warp;
    if (i >= NN) return;

    const float4* hbase = (const float4*)g_h1;
    int deg = g_cursor[i]; if (deg > MAXDEG) deg = MAXDEG;
    int base = i * MAXDEG;
    float adi = g_ad1[i];
    float w_self = __expf(leaky(g_as1[i] + adi));
    float acc[12];
    if (grp == 0) {
        const float4* hp = hbase + i * 24 + sub * 3;
#pragma unroll
        for (int k = 0; k < 3; k++) {
            float4 v = hp[k];
            acc[4 * k] = w_self * v.x; acc[4 * k + 1] = w_self * v.y;
            acc[4 * k + 2] = w_self * v.z; acc[4 * k + 3] = w_self * v.w;
        }
    } else {
#pragma unroll
        for (int q = 0; q < 12; q++) acc[q] = 0.f;
    }
    float dsum = (lane == 0) ? w_self : 0.f;

    for (int j0 = 0; j0 < deg; j0 += 32) {
        int jj = j0 + lane;
        int cnt = deg - j0; if (cnt > 32) cnt = 32;
        int s = (jj < deg) ? g_csrc[base + jj] : 0;
        float w = (jj < deg) ? __expf(leaky(g_as1[s] + adi)) : 0.f;
        dsum += w;
        int nst = (cnt + 3) >> 2;
        for (int t = 0; t < nst; t++) {
            int e = t * 4 + grp;
            int ss = __shfl_sync(~0u, s, e);
            float ww = __shfl_sync(~0u, w, e);
            if (e < cnt) {
                const float4* hp = hbase + ss * 24 + sub * 3;
#pragma unroll
                for (int k = 0; k < 3; k++) {
                    float4 v = hp[k];
                    acc[4 * k] += ww * v.x; acc[4 * k + 1] += ww * v.y;
                    acc[4 * k + 2] += ww * v.z; acc[4 * k + 3] += ww * v.w;
                }
            }
        }
    }
#pragma unroll
    for (int o = 16; o; o >>= 1) dsum += __shfl_xor_sync(~0u, dsum, o);
#pragma unroll
    for (int q = 0; q < 12; q++) {
        acc[q] += __shfl_xor_sync(~0u, acc[q], 8);
        acc[q] += __shfl_xor_sync(~0u, acc[q], 16);
    }
    float inv = 1.f / dsum;
    float o[12];
#pragma unroll
    for (int q = 0; q < 12; q++) {
        float v = acc[q] * inv + sb1[sub * 12 + q];
        o[q] = v > 0.f ? v : (__expf(v) - 1.f);
    }
    if (lane < 8) {
#pragma unroll
        for (int q = 0; q < 12; q++) sh1e[warp][lane * 12 + q] = o[q];
    }
    __syncwarp();
    float a2 = 0.f;
#pragma unroll 16
    for (int k = 0; k < HID; k++) a2 += sh1e[warp][k] * ws[k * NCLS + lane];
    g_h2[i * NCLS + lane] = a2;
    float s1 = a2 * sa2[lane], s2 = a2 * sd2[lane];
#pragma unroll
    for (int off = 16; off; off >>= 1) {
        s1 += __shfl_xor_sync(~0u, s1, off);
        s2 += __shfl_xor_sync(~0u, s2, off);
    }
    if (lane == 0) { g_as2[i] = s1; g_ad2[i] = s2; }
}

// 4: layer-2 agg + bias + log_softmax -> out
__global__ void __launch_bounds__(256) k_agg2(const float* __restrict__ b2,
                                              float* __restrict__ outp) {
    int tid = threadIdx.x;
    int warp = tid >> 5, lane = tid & 31;
    int grp = lane >> 3, sub = lane & 7;
    int i = blockIdx.x * 8 + warp;
    if (i >= NN) return;
    const float4* hbase = (const float4*)g_h2;
    int deg = g_cursor[i]; if (deg > MAXDEG) deg = MAXDEG;
    int base = i * MAXDEG;
    float adi = g_ad2[i];
    float w_self = __expf(leaky(g_as2[i] + adi));
    float acc[4];
    if (grp == 0) {
        float4 v = hbase[i * 8 + sub];
        acc[0] = w_self * v.x; acc[1] = w_self * v.y;
        acc[2] = w_self * v.z; acc[3] = w_self * v.w;
    } else {
        acc[0] = acc[1] = acc[2] = acc[3] = 0.f;
    }
    float dsum = (lane == 0) ? w_self : 0.f;
    for (int j0 = 0; j0 < deg; j0 += 32) {
        int jj = j0 + lane;
        int cnt = deg - j0; if (cnt > 32) cnt = 32;
        int s = (jj < deg) ? g_csrc[base + jj] : 0;
        float w = (jj < deg) ? __expf(leaky(g_as2[s] + adi)) : 0.f;
        dsum += w;
        int nst = (cnt + 3) >> 2;
        for (int t = 0; t < nst; t++) {
            int e = t * 4 + grp;
            int ss = __shfl_sync(~0u, s, e);
            float ww = __shfl_sync(~0u, w, e);
            if (e < cnt) {
                float4 v = hbase[ss * 8 + sub];
                acc[0] += ww * v.x; acc[1] += ww * v.y;
                acc[2] += ww * v.z; acc[3] += ww * v.w;
            }
        }
    }
#pragma unroll
    for (int o = 16; o; o >>= 1) dsum += __shfl_xor_sync(~0u, dsum, o);
#pragma unroll
    for (int q = 0; q < 4; q++) {
        acc[q] += __shfl_xor_sync(~0u, acc[q], 8);
        acc[q] += __shfl_xor_sync(~0u, acc[q], 16);
    }
    float inv = 1.f / dsum;
    float o[4];
    float mx = -1e30f;
#pragma unroll
    for (int q = 0; q < 4; q++) {
        o[q] = acc[q] * inv + b2[sub * 4 + q];
        mx = fmaxf(mx, o[q]);
    }
#pragma unroll
    for (int off = 1; off < 8; off <<= 1) mx = fmaxf(mx, __shfl_xor_sync(~0u, mx, off));
    float se = 0.f;
#pragma unroll
    for (int q = 0; q < 4; q++) se += __expf(o[q] - mx);
#pragma unroll
    for (int off = 1; off < 8; off <<= 1) se += __shfl_xor_sync(~0u, se, off);
    float lse = mx + __logf(se);
    if (lane < 8) {
        float4 r = make_float4(o[0] - lse, o[1] - lse, o[2] - lse, o[3] - lse);
        *((float4*)(outp + i * NCLS) + sub) = r;
    }
}

// ---------------- launch -----------------------------------------------------
extern "C" void kernel_launch(void* const* d_in, const int* in_sizes, int n_in,
                              void* d_out, int out_size) {
    const float* x   = (const float*)d_in[0];
    const void*  ei  = d_in[1];
    const float* W1  = (const float*)d_in[2];
    const float* a1s = (const float*)d_in[3];
    const float* a1d = (const float*)d_in[4];
    const float* b1  = (const float*)d_in[5];
    const float* W2  = (const float*)d_in[6];
    const float* a2s = (const float*)d_in[7];
    const float* a2d = (const float*)d_in[8];
    const float* b2  = (const float*)d_in[9];
    float* out = (float*)d_out;

    k_gemm1<<<GEMM_BLKS + AUX_BLKS, 256>>>(x, W1);              // 0 (gemm + zero cursor)
    k_scatter_alpha<<<NB_ROWS + NB_SCAT4, 256>>>(ei, a1s, a1d); // 1
    k_agg1<<<NB_ROWS, 256>>>(b1, W2, a2s, a2d);                 // 2
    k_agg2<<<NB_ROWS, 256>>>(b2, out);                          // 3
}